// round 12
// baseline (speedup 1.0000x reference)
#include <cuda_runtime.h>
#include <cuda_fp16.h>
#include <math.h>
#include <cstdint>

#define T 4096
#define HD 1024
#define ID 2048
#define NE 8
#define NK 2
#define ROWS_R (T * NK)          /* 8192 routed rows (t*2+k) */
#define ROWS_ALL (ROWS_R + T)    /* + 4096 shared rows       */

#define OUT_AUX ((size_t)T * HD)
#define OUT_Z (OUT_AUX + 1)
#define OUT_LOGITS (OUT_Z + 1)

#define BM 128
#define BKC 64                   /* k-chunk (fp16 elems) = 128 bytes */
#define NC1 (HD / BKC)           /* 16 iters gemm1 */
#define NC2 (ID / BKC)           /* 32 iters gemm2 */
#define RSB 144                  /* smem row stride bytes: banks 4i..4i+3 -> conflict-free */

// smem plane: 128 rows * 144B = 18432; buffer = A | B (2 planes)
#define PL 18432
#define BUFB (2 * PL)            /* 36864 */
#define SM_TOK 0
#define SM_SLOT 512
#define SM_BUF0 1024
#define SMEM_BYTES (1024 + 2 * BUFB)   /* 74752 */

#define ROUTER_BLOCKS (T / 8)    /* 512 */
#define CONVW_BLOCKS (27 * 2048) /* 55296 */

typedef unsigned long long u64;

// ---------------- device scratch (static; no allocs allowed) ----------------
__device__ __half g_wg[(size_t)9 * ID * HD];    // gate  [e][n][k] fp16
__device__ __half g_wu[(size_t)9 * ID * HD];    // up    [e][n][k] fp16
__device__ __half g_wd[(size_t)9 * HD * ID];    // down  [e][n][k] fp16
__device__ __half g_x[(size_t)T * HD];          // x fp16
__device__ __half g_act[(size_t)ROWS_ALL * ID]; // silu(gate)*up fp16
__device__ float g_y[(size_t)ROWS_ALL * HD];
__device__ int   g_elist[NE * T];
__device__ int   g_count[NE];
__device__ float g_wslot[T * NK];
__device__ float g_probsum[NE];
__device__ float g_zsum;

// ---------------- PTX helpers (plain sm_103-safe) ----------------
static __device__ __forceinline__ uint32_t s2u(const void* p) {
    uint32_t a;
    asm("{ .reg .u64 t; cvta.to.shared.u64 t, %1; cvt.u32.u64 %0, t; }"
        : "=r"(a) : "l"(p));
    return a;
}

#define CPA16(sa, ga) \
    asm volatile("cp.async.cg.shared.global [%0], [%1], 16;" \
        :: "r"((uint32_t)(sa)), "l"(ga) : "memory")
#define CP_COMMIT() asm volatile("cp.async.commit_group;" ::: "memory")
#define CP_WAIT1()  asm volatile("cp.async.wait_group 1;" ::: "memory")

static __device__ __forceinline__ void ldsm4(uint32_t* r, uint32_t a) {
    asm volatile("ldmatrix.sync.aligned.m8n8.x4.shared.b16 {%0,%1,%2,%3}, [%4];"
        : "=r"(r[0]), "=r"(r[1]), "=r"(r[2]), "=r"(r[3]) : "r"(a));
}

static __device__ __forceinline__ void mma16816(float* d, const uint32_t* a,
                                                const uint32_t* b) {
    asm volatile(
        "mma.sync.aligned.m16n8k16.row.col.f32.f16.f16.f32 "
        "{%0,%1,%2,%3}, {%4,%5,%6,%7}, {%8,%9}, {%0,%1,%2,%3};"
        : "+f"(d[0]), "+f"(d[1]), "+f"(d[2]), "+f"(d[3])
        : "r"(a[0]), "r"(a[1]), "r"(a[2]), "r"(a[3]), "r"(b[0]), "r"(b[1]));
}

// ============================================================
__global__ void reset_kernel() {
    int i = threadIdx.x;
    if (i < NE) { g_count[i] = 0; g_probsum[i] = 0.f; }
    if (i == 0) g_zsum = 0.f;
}

// ============================================================
// fused pre-kernel: blocks [0,512) = router (+x->fp16), blocks
// [512, 512+55296) = weight convert+transpose. Roles independent.
// ============================================================
__global__ void fused_pre_kernel(const float* __restrict__ x,
                                 const float* __restrict__ rw,
                                 float* __restrict__ out,
                                 const float* __restrict__ gw,
                                 const float* __restrict__ uw,
                                 const float* __restrict__ dw,
                                 const float* __restrict__ sgw,
                                 const float* __restrict__ suw,
                                 const float* __restrict__ sdw) {
    __shared__ float sf[HD * 9 + NE + 1];   // router: srw | sp | sz ; convw: tile
    int tid = threadIdx.x;

    if (blockIdx.x < ROUTER_BLOCKS) {
        // ---------------- router role ----------------
        float* srw = sf;
        float* sp = sf + HD * 9;
        float* szp = sf + HD * 9 + NE;
        int warp = tid >> 5;
        int lane = tid & 31;
        int t = blockIdx.x * 8 + warp;

#pragma unroll
        for (int i = 0; i < 8; i++) {
            int f = tid + i * 256;
            float4 v = ((const float4*)rw)[f];
            int h = f >> 1;
            int e0 = (f & 1) * 4;
            srw[h * 9 + e0 + 0] = v.x;
            srw[h * 9 + e0 + 1] = v.y;
            srw[h * 9 + e0 + 2] = v.z;
            srw[h * 9 + e0 + 3] = v.w;
        }
        if (tid < NE) sp[tid] = 0.f;
        if (tid == NE) *szp = 0.f;
        __syncthreads();

        const float* xr = x + (size_t)t * HD;
        __half* gx = g_x + (size_t)t * HD;
        float acc[NE];
#pragma unroll
        for (int e = 0; e < NE; e++) acc[e] = 0.f;
#pragma unroll 8
        for (int i = 0; i < 32; i++) {
            int h = lane + i * 32;
            float xv = xr[h];
            gx[h] = __float2half_rn(xv);
            const float* r = &srw[h * 9];
#pragma unroll
            for (int e = 0; e < NE; e++) acc[e] = fmaf(xv, r[e], acc[e]);
        }
#pragma unroll
        for (int off = 16; off; off >>= 1) {
#pragma unroll
            for (int e = 0; e < NE; e++)
                acc[e] += __shfl_xor_sync(0xffffffffu, acc[e], off);
        }

        if (lane == 0) {
            float m = acc[0];
#pragma unroll
            for (int e = 1; e < NE; e++) m = fmaxf(m, acc[e]);
            float s = 0.f;
#pragma unroll
            for (int e = 0; e < NE; e++) s += expf(acc[e] - m);
            float lse = m + logf(s);
            float p[NE];
#pragma unroll
            for (int e = 0; e < NE; e++) p[e] = expf(acc[e] - lse);

            int i0 = 0;
#pragma unroll
            for (int e = 1; e < NE; e++) if (p[e] > p[i0]) i0 = e;
            int i1 = (i0 == 0) ? 1 : 0;
#pragma unroll
            for (int e = 0; e < NE; e++)
                if (e != i1 && e != i0 && p[e] > p[i1]) i1 = e;

            float sum2 = p[i0] + p[i1];
            g_wslot[2 * t]     = p[i0] / sum2;
            g_wslot[2 * t + 1] = p[i1] / sum2;

            int pos0 = atomicAdd(&g_count[i0], 1);
            g_elist[i0 * T + pos0] = 2 * t;
            int pos1 = atomicAdd(&g_count[i1], 1);
            g_elist[i1 * T + pos1] = 2 * t + 1;

#pragma unroll
            for (int e = 0; e < NE; e++) {
                out[OUT_LOGITS + (size_t)t * NE + e] = acc[e];
                atomicAdd(&sp[e], p[e]);
            }
            atomicAdd(szp, lse * lse);
        }
        __syncthreads();
        if (tid < NE) atomicAdd(&g_probsum[tid], sp[tid]);
        if (tid == NE) atomicAdd(&g_zsum, *szp);
    } else {
        // ---------------- convw role ----------------
        int b2 = blockIdx.x - ROUTER_BLOCKS;
        int z = b2 >> 11;                    // /2048
        int rem = b2 & 2047;
        int bx = rem & 63;
        int by = rem >> 6;
        int mat = z / 9;
        int e = z % 9;
        __half* dst;
        const float* src;
        int K, N, n0, k0;
        if (mat == 0) {
            dst = g_wg; src = (e < NE) ? gw + (size_t)e * HD * ID : sgw;
            K = HD; N = ID; n0 = bx * 32; k0 = by * 32;
        } else if (mat == 1) {
            dst = g_wu; src = (e < NE) ? uw + (size_t)e * HD * ID : suw;
            K = HD; N = ID; n0 = bx * 32; k0 = by * 32;
        } else {
            dst = g_wd; src = (e < NE) ? dw + (size_t)e * ID * HD : sdw;
            K = ID; N = HD; n0 = by * 32; k0 = bx * 32;
        }
        float (*tile)[33] = (float (*)[33])sf;
        {
            int row = tid >> 3, f4 = tid & 7;
            float4 v = *(const float4*)(src + (size_t)(k0 + row) * N + n0 + f4 * 4);
            tile[row][f4 * 4 + 0] = v.x;
            tile[row][f4 * 4 + 1] = v.y;
            tile[row][f4 * 4 + 2] = v.z;
            tile[row][f4 * 4 + 3] = v.w;
        }
        __syncthreads();
        {
            int nr = tid >> 3, seg = tid & 7;
            int k = seg * 4;
            __half2 a, b;
            a.x = __float2half_rn(tile[k + 0][nr]);
            a.y = __float2half_rn(tile[k + 1][nr]);
            b.x = __float2half_rn(tile[k + 2][nr]);
            b.y = __float2half_rn(tile[k + 3][nr]);
            uint2 pk;
            pk.x = *(uint32_t*)&a;
            pk.y = *(uint32_t*)&b;
            *(uint2*)(dst + (size_t)e * K * N + (size_t)(n0 + nr) * K + k0 + k) = pk;
        }
    }
}

// ============================================================
// GEMM1 (mma.sync fp16): per CTA 128 rows x 64 cols of BOTH gate and up;
// fused SiLU epilogue -> g_act fp16. BKC=64. smem: A | B(gate 0-63, up 64-127)
// ============================================================
__global__ __launch_bounds__(256) void gemm1_tc() {
    int e = blockIdx.z;
    int n = (e < NE) ? g_count[e] : T;
    int row0 = blockIdx.x * BM;
    if (row0 >= n) return;
    int j0 = blockIdx.y * 64;
    int tid = threadIdx.x;
    int lane = tid & 31;
    int wid = tid >> 5;
    int wm = wid & 3;            // M: 4 warps
    int wn = wid >> 2;           // N: 2 warps (32 cols each)

    extern __shared__ char smem[];
    uint32_t sb = s2u(smem);
    int* s_tok = (int*)(smem + SM_TOK);
    int* s_slot = (int*)(smem + SM_SLOT);

    if (tid < BM) {
        int pos = row0 + tid;
        int slot, tok;
        if (pos < n) {
            if (e < NE) { slot = g_elist[e * T + pos]; tok = slot >> 1; }
            else        { slot = ROWS_R + pos;         tok = pos; }
        } else {
            slot = -1;
            tok = (e < NE) ? (g_elist[e * T + row0] >> 1) : row0;
        }
        s_slot[tid] = slot;
        s_tok[tid] = tok;
    }
    __syncthreads();

    // loader: row = tid>>1, 64B half per thread (4 x CPA16)
    int lrow = tid >> 1;
    int lb = (tid & 1) * 64;
    uint32_t loff = (uint32_t)(lrow * RSB + lb);
    const char* pA = (const char*)(g_x + (size_t)s_tok[lrow] * HD) + lb;
    const char* pB = (lrow < 64)
        ? (const char*)(g_wg + ((size_t)e * ID + j0 + lrow) * HD) + lb
        : (const char*)(g_wu + ((size_t)e * ID + j0 + lrow - 64) * HD) + lb;

#define G1_LOAD(bb) do { \
    CPA16((bb) + loff,      pA);      CPA16((bb) + loff + 16, pA + 16); \
    CPA16((bb) + loff + 32, pA + 32); CPA16((bb) + loff + 48, pA + 48); \
    CPA16((bb) + PL + loff,      pB);      CPA16((bb) + PL + loff + 16, pB + 16); \
    CPA16((bb) + PL + loff + 32, pB + 32); CPA16((bb) + PL + loff + 48, pB + 48); \
    pA += 128; pB += 128; \
    CP_COMMIT(); } while (0)

    float accg[2][4][4], accu[2][4][4];
#pragma unroll
    for (int mt = 0; mt < 2; mt++)
#pragma unroll
        for (int nt = 0; nt < 4; nt++)
#pragma unroll
            for (int c = 0; c < 4; c++) { accg[mt][nt][c] = 0.f; accu[mt][nt][c] = 0.f; }

    int lr = lane & 7;
    int aro = ((lane >> 3) & 1) * 8 + lr;     // A row-in-16
    int akb = (lane >> 4) * 16;               // A k-byte half
    int bro = ((lane >> 4) & 1) * 8 + lr;     // B row-in-16
    int bkb = ((lane >> 3) & 1) * 16;         // B k-byte half

    G1_LOAD(sb + SM_BUF0);

    for (int c = 0; c < NC1; c++) {
        if (c + 1 < NC1) G1_LOAD(sb + SM_BUF0 + ((c + 1) & 1) * BUFB);
        else CP_COMMIT();
        CP_WAIT1();
        __syncthreads();
        uint32_t bb = sb + SM_BUF0 + (c & 1) * BUFB;

#pragma unroll
        for (int ks = 0; ks < 4; ks++) {
            int kb = ks * 32;
            uint32_t ah[2][4];
#pragma unroll
            for (int mt = 0; mt < 2; mt++) {
                uint32_t ra = bb + (uint32_t)((wm * 32 + mt * 16 + aro) * RSB) + kb + akb;
                ldsm4(ah[mt], ra);
            }
            uint32_t bg[4][2], bu[4][2];
#pragma unroll
            for (int p = 0; p < 2; p++) {
                uint32_t rb = bb + PL + (uint32_t)((wn * 32 + p * 16 + bro) * RSB) + kb + bkb;
                uint32_t rg[4];
                ldsm4(rg, rb);
                bg[2 * p][0] = rg[0]; bg[2 * p][1] = rg[1];
                bg[2 * p + 1][0] = rg[2]; bg[2 * p + 1][1] = rg[3];
                ldsm4(rg, rb + 64 * RSB);
                bu[2 * p][0] = rg[0]; bu[2 * p][1] = rg[1];
                bu[2 * p + 1][0] = rg[2]; bu[2 * p + 1][1] = rg[3];
            }
#pragma unroll
            for (int mt = 0; mt < 2; mt++)
#pragma unroll
                for (int nt = 0; nt < 4; nt++) {
                    mma16816(accg[mt][nt], ah[mt], bg[nt]);
                    mma16816(accu[mt][nt], ah[mt], bu[nt]);
                }
        }
        __syncthreads();
    }
#undef G1_LOAD

    // ---- epilogue: silu(gate)*up -> fp16 ----
#pragma unroll
    for (int mt = 0; mt < 2; mt++) {
        int rA = wm * 32 + mt * 16 + (lane >> 2);
        int sl0 = s_slot[rA], sl1 = s_slot[rA + 8];
#pragma unroll
        for (int nt = 0; nt < 4; nt++) {
            int col = j0 + wn * 32 + nt * 8 + (lane & 3) * 2;
#pragma unroll
            for (int hhalf = 0; hhalf < 2; hhalf++) {
                int sl = hhalf ? sl1 : sl0;
                if (sl < 0) continue;
                float g0 = accg[mt][nt][hhalf * 2], g1 = accg[mt][nt][hhalf * 2 + 1];
                float u0 = accu[mt][nt][hhalf * 2], u1 = accu[mt][nt][hhalf * 2 + 1];
                float a0 = (g0 * u0) / (1.0f + __expf(-g0));
                float a1 = (g1 * u1) / (1.0f + __expf(-g1));
                __half2 hh;
                hh.x = __float2half_rn(a0); hh.y = __float2half_rn(a1);
                *(__half2*)(g_act + (size_t)sl * ID + col) = hh;
            }
        }
    }
}

// ============================================================
// GEMM2 (mma.sync fp16): per CTA 128 rows x 128 cols -> g_y fp32. BKC=64.
// ============================================================
__global__ __launch_bounds__(256) void gemm2_tc() {
    int e = blockIdx.z;
    int n = (e < NE) ? g_count[e] : T;
    int row0 = blockIdx.x * BM;
    if (row0 >= n) return;
    int j0 = blockIdx.y * 128;
    int tid = threadIdx.x;
    int lane = tid & 31;
    int wid = tid >> 5;
    int wm = wid & 3;
    int wn = wid >> 2;           // 2 warps x 64 cols

    extern __shared__ char smem[];
    uint32_t sb = s2u(smem);
    int* s_arow = (int*)(smem + SM_TOK);
    int* s_slot = (int*)(smem + SM_SLOT);

    if (tid < BM) {
        int pos = row0 + tid;
        int slot;
        if (pos < n) slot = (e < NE) ? g_elist[e * T + pos] : (ROWS_R + pos);
        else         slot = -1;
        s_slot[tid] = slot;
        s_arow[tid] = (slot >= 0) ? slot
                                  : ((e < NE) ? g_elist[e * T + row0] : (ROWS_R + row0));
    }
    __syncthreads();

    int lrow = tid >> 1;
    int lb = (tid & 1) * 64;
    uint32_t loff = (uint32_t)(lrow * RSB + lb);
    const char* pA = (const char*)(g_act + (size_t)s_arow[lrow] * ID) + lb;
    const char* pB = (const char*)(g_wd + ((size_t)e * HD + j0 + lrow) * ID) + lb;

#define G2_LOAD(bb) do { \
    CPA16((bb) + loff,      pA);      CPA16((bb) + loff + 16, pA + 16); \
    CPA16((bb) + loff + 32, pA + 32); CPA16((bb) + loff + 48, pA + 48); \
    CPA16((bb) + PL + loff,      pB);      CPA16((bb) + PL + loff + 16, pB + 16); \
    CPA16((bb) + PL + loff + 32, pB + 32); CPA16((bb) + PL + loff + 48, pB + 48); \
    pA += 128; pB += 128; \
    CP_COMMIT(); } while (0)

    float acc[2][8][4];
#pragma unroll
    for (int mt = 0; mt < 2; mt++)
#pragma unroll
        for (int nt = 0; nt < 8; nt++)
#pragma unroll
            for (int c = 0; c < 4; c++) acc[mt][nt][c] = 0.f;

    int lr = lane & 7;
    int aro = ((lane >> 3) & 1) * 8 + lr;
    int akb = (lane >> 4) * 16;
    int bro = ((lane >> 4) & 1) * 8 + lr;
    int bkb = ((lane >> 3) & 1) * 16;

    G2_LOAD(sb + SM_BUF0);

    for (int c = 0; c < NC2; c++) {
        if (c + 1 < NC2) G2_LOAD(sb + SM_BUF0 + ((c + 1) & 1) * BUFB);
        else CP_COMMIT();
        CP_WAIT1();
        __syncthreads();
        uint32_t bb = sb + SM_BUF0 + (c & 1) * BUFB;

#pragma unroll
        for (int ks = 0; ks < 4; ks++) {
            int kb = ks * 32;
            uint32_t ah[2][4];
#pragma unroll
            for (int mt = 0; mt < 2; mt++) {
                uint32_t ra = bb + (uint32_t)((wm * 32 + mt * 16 + aro) * RSB) + kb + akb;
                ldsm4(ah[mt], ra);
            }
            uint32_t bh[8][2];
#pragma unroll
            for (int p = 0; p < 4; p++) {
                uint32_t rb = bb + PL + (uint32_t)((wn * 64 + p * 16 + bro) * RSB) + kb + bkb;
                uint32_t rg[4];
                ldsm4(rg, rb);
                bh[2 * p][0] = rg[0]; bh[2 * p][1] = rg[1];
                bh[2 * p + 1][0] = rg[2]; bh[2 * p + 1][1] = rg[3];
            }
#pragma unroll
            for (int mt = 0; mt < 2; mt++)
#pragma unroll
                for (int nt = 0; nt < 8; nt++)
                    mma16816(acc[mt][nt], ah[mt], bh[nt]);
        }
        __syncthreads();
    }
#undef G2_LOAD

    // ---- epilogue: fp32 stores to g_y ----
#pragma unroll
    for (int mt = 0; mt < 2; mt++) {
        int rA = wm * 32 + mt * 16 + (lane >> 2);
        int sl0 = s_slot[rA], sl1 = s_slot[rA + 8];
#pragma unroll
        for (int nt = 0; nt < 8; nt++) {
            int col = j0 + wn * 64 + nt * 8 + (lane & 3) * 2;
            if (sl0 >= 0) {
                float2 v; v.x = acc[mt][nt][0]; v.y = acc[mt][nt][1];
                *(float2*)(g_y + (size_t)sl0 * HD + col) = v;
            }
            if (sl1 >= 0) {
                float2 v; v.x = acc[mt][nt][2]; v.y = acc[mt][nt][3];
                *(float2*)(g_y + (size_t)sl1 * HD + col) = v;
            }
        }
    }
}

// ============================================================
// combine: out[t] = w0*y[2t] + w1*y[2t+1] + y_shared[t]  (+ finalize in blk 0)
// ============================================================
__global__ void combine_kernel(float* __restrict__ out) {
    if (blockIdx.x == 0 && threadIdx.x == 0) {
        float aux = 0.f;
#pragma unroll
        for (int e = 0; e < NE; e++)
            aux += ((float)g_count[e] / (2.0f * (float)T)) * (g_probsum[e] / (float)T);
        out[OUT_AUX] = (float)NE * aux;
        out[OUT_Z] = g_zsum / (float)T;
    }
    int idx = blockIdx.x * blockDim.x + threadIdx.x;
    int t = idx / (HD / 4);
    int c = (idx % (HD / 4)) * 4;
    float w0 = g_wslot[2 * t];
    float w1 = g_wslot[2 * t + 1];
    float4 y0 = *(const float4*)(g_y + (size_t)(2 * t) * HD + c);
    float4 y1 = *(const float4*)(g_y + (size_t)(2 * t + 1) * HD + c);
    float4 ys = *(const float4*)(g_y + (size_t)(ROWS_R + t) * HD + c);
    float4 r;
    r.x = fmaf(w0, y0.x, fmaf(w1, y1.x, ys.x));
    r.y = fmaf(w0, y0.y, fmaf(w1, y1.y, ys.y));
    r.z = fmaf(w0, y0.z, fmaf(w1, y1.z, ys.z));
    r.w = fmaf(w0, y0.w, fmaf(w1, y1.w, ys.w));
    *(float4*)(out + (size_t)t * HD + c) = r;
}

// ============================================================
extern "C" void kernel_launch(void* const* d_in, const int* in_sizes, int n_in,
                              void* d_out, int out_size) {
    const float* x   = (const float*)d_in[0];
    const float* rw  = (const float*)d_in[1];
    const float* gw  = (const float*)d_in[2];
    const float* uw  = (const float*)d_in[3];
    const float* dw  = (const float*)d_in[4];
    const float* sgw = (const float*)d_in[5];
    const float* suw = (const float*)d_in[6];
    const float* sdw = (const float*)d_in[7];
    float* out = (float*)d_out;

    cudaFuncSetAttribute(gemm1_tc, cudaFuncAttributeMaxDynamicSharedMemorySize, SMEM_BYTES);
    cudaFuncSetAttribute(gemm2_tc, cudaFuncAttributeMaxDynamicSharedMemorySize, SMEM_BYTES);

    reset_kernel<<<1, 32>>>();
    fused_pre_kernel<<<ROUTER_BLOCKS + CONVW_BLOCKS, 256>>>(
        x, rw, out, gw, uw, dw, sgw, suw, sdw);
    gemm1_tc<<<dim3(T / BM, ID / 64, NE + 1), 256, SMEM_BYTES>>>();
    gemm2_tc<<<dim3(T / BM, HD / 128, NE + 1), 256, SMEM_BYTES>>>();
    combine_kernel<<<(T * HD / 4) / 256, 256>>>(out);
}

// round 13
// speedup vs baseline: 1.2868x; 1.2868x over previous
#include <cuda_runtime.h>
#include <cuda_fp16.h>
#include <math.h>
#include <cstdint>

#define T 4096
#define HD 1024
#define ID 2048
#define NE 8
#define NK 2
#define ROWS_R (T * NK)          /* 8192 routed rows (t*2+k) */
#define ROWS_ALL (ROWS_R + T)    /* + 4096 shared rows       */

#define OUT_AUX ((size_t)T * HD)
#define OUT_Z (OUT_AUX + 1)
#define OUT_LOGITS (OUT_Z + 1)

#define BM 128
#define BKC 32                   /* k-chunk (fp16 elems) = 64 bytes */
#define NC1 (HD / BKC)           /* 32 iters gemm1 */
#define NC2 (ID / BKC)           /* 64 iters gemm2 */
#define RSB 80                   /* smem row stride bytes (conflict-free) */

// smem plane: 128 rows * 80B = 10240; buffer = A | B (2 planes); 4 stages
#define PL 10240
#define BUFB (2 * PL)            /* 20480 */
#define NSTG 4
#define SM_TOK 0
#define SM_SLOT 512
#define SM_BUF0 1024
#define SMEM_BYTES (1024 + NSTG * BUFB)   /* 82944 */

#define ROUTER_BLOCKS (T / 8)    /* 512 */
#define CONVW_BLOCKS (27 * 2048) /* 55296 */

typedef unsigned long long u64;

// ---------------- device scratch (static; no allocs allowed) ----------------
__device__ __half g_wg[(size_t)9 * ID * HD];    // gate  [e][n][k] fp16
__device__ __half g_wu[(size_t)9 * ID * HD];    // up    [e][n][k] fp16
__device__ __half g_wd[(size_t)9 * HD * ID];    // down  [e][n][k] fp16
__device__ __half g_x[(size_t)T * HD];          // x fp16
__device__ __half g_act[(size_t)ROWS_ALL * ID]; // silu(gate)*up fp16
__device__ float g_y[(size_t)ROWS_ALL * HD];
__device__ int   g_elist[NE * T];
__device__ int   g_count[NE];
__device__ float g_wslot[T * NK];
__device__ float g_probsum[NE];
__device__ float g_zsum;

// ---------------- PTX helpers (plain sm_103-safe) ----------------
static __device__ __forceinline__ uint32_t s2u(const void* p) {
    uint32_t a;
    asm("{ .reg .u64 t; cvta.to.shared.u64 t, %1; cvt.u32.u64 %0, t; }"
        : "=r"(a) : "l"(p));
    return a;
}

#define CPA16(sa, ga) \
    asm volatile("cp.async.cg.shared.global [%0], [%1], 16;" \
        :: "r"((uint32_t)(sa)), "l"(ga) : "memory")
#define CP_COMMIT() asm volatile("cp.async.commit_group;" ::: "memory")
#define CP_WAIT3()  asm volatile("cp.async.wait_group 3;" ::: "memory")

static __device__ __forceinline__ void ldsm4(uint32_t* r, uint32_t a) {
    asm volatile("ldmatrix.sync.aligned.m8n8.x4.shared.b16 {%0,%1,%2,%3}, [%4];"
        : "=r"(r[0]), "=r"(r[1]), "=r"(r[2]), "=r"(r[3]) : "r"(a));
}

static __device__ __forceinline__ void mma16816(float* d, const uint32_t* a,
                                                const uint32_t* b) {
    asm volatile(
        "mma.sync.aligned.m16n8k16.row.col.f32.f16.f16.f32 "
        "{%0,%1,%2,%3}, {%4,%5,%6,%7}, {%8,%9}, {%0,%1,%2,%3};"
        : "+f"(d[0]), "+f"(d[1]), "+f"(d[2]), "+f"(d[3])
        : "r"(a[0]), "r"(a[1]), "r"(a[2]), "r"(a[3]), "r"(b[0]), "r"(b[1]));
}

// ============================================================
__global__ void reset_kernel() {
    int i = threadIdx.x;
    if (i < NE) { g_count[i] = 0; g_probsum[i] = 0.f; }
    if (i == 0) g_zsum = 0.f;
}

// ============================================================
// fused pre-kernel: blocks [0,512) = router (+x->fp16), blocks
// [512, 512+55296) = weight convert+transpose. Roles independent.
// ============================================================
__global__ void fused_pre_kernel(const float* __restrict__ x,
                                 const float* __restrict__ rw,
                                 float* __restrict__ out,
                                 const float* __restrict__ gw,
                                 const float* __restrict__ uw,
                                 const float* __restrict__ dw,
                                 const float* __restrict__ sgw,
                                 const float* __restrict__ suw,
                                 const float* __restrict__ sdw) {
    __shared__ float sf[HD * 9 + NE + 1];   // router: srw | sp | sz ; convw: tile
    int tid = threadIdx.x;

    if (blockIdx.x < ROUTER_BLOCKS) {
        // ---------------- router role ----------------
        float* srw = sf;
        float* sp = sf + HD * 9;
        float* szp = sf + HD * 9 + NE;
        int warp = tid >> 5;
        int lane = tid & 31;
        int t = blockIdx.x * 8 + warp;

#pragma unroll
        for (int i = 0; i < 8; i++) {
            int f = tid + i * 256;
            float4 v = ((const float4*)rw)[f];
            int h = f >> 1;
            int e0 = (f & 1) * 4;
            srw[h * 9 + e0 + 0] = v.x;
            srw[h * 9 + e0 + 1] = v.y;
            srw[h * 9 + e0 + 2] = v.z;
            srw[h * 9 + e0 + 3] = v.w;
        }
        if (tid < NE) sp[tid] = 0.f;
        if (tid == NE) *szp = 0.f;
        __syncthreads();

        const float* xr = x + (size_t)t * HD;
        __half* gx = g_x + (size_t)t * HD;
        float acc[NE];
#pragma unroll
        for (int e = 0; e < NE; e++) acc[e] = 0.f;
#pragma unroll 8
        for (int i = 0; i < 32; i++) {
            int h = lane + i * 32;
            float xv = xr[h];
            gx[h] = __float2half_rn(xv);
            const float* r = &srw[h * 9];
#pragma unroll
            for (int e = 0; e < NE; e++) acc[e] = fmaf(xv, r[e], acc[e]);
        }
#pragma unroll
        for (int off = 16; off; off >>= 1) {
#pragma unroll
            for (int e = 0; e < NE; e++)
                acc[e] += __shfl_xor_sync(0xffffffffu, acc[e], off);
        }

        if (lane == 0) {
            float m = acc[0];
#pragma unroll
            for (int e = 1; e < NE; e++) m = fmaxf(m, acc[e]);
            float s = 0.f;
#pragma unroll
            for (int e = 0; e < NE; e++) s += expf(acc[e] - m);
            float lse = m + logf(s);
            float p[NE];
#pragma unroll
            for (int e = 0; e < NE; e++) p[e] = expf(acc[e] - lse);

            int i0 = 0;
#pragma unroll
            for (int e = 1; e < NE; e++) if (p[e] > p[i0]) i0 = e;
            int i1 = (i0 == 0) ? 1 : 0;
#pragma unroll
            for (int e = 0; e < NE; e++)
                if (e != i1 && e != i0 && p[e] > p[i1]) i1 = e;

            float sum2 = p[i0] + p[i1];
            g_wslot[2 * t]     = p[i0] / sum2;
            g_wslot[2 * t + 1] = p[i1] / sum2;

            int pos0 = atomicAdd(&g_count[i0], 1);
            g_elist[i0 * T + pos0] = 2 * t;
            int pos1 = atomicAdd(&g_count[i1], 1);
            g_elist[i1 * T + pos1] = 2 * t + 1;

#pragma unroll
            for (int e = 0; e < NE; e++) {
                out[OUT_LOGITS + (size_t)t * NE + e] = acc[e];
                atomicAdd(&sp[e], p[e]);
            }
            atomicAdd(szp, lse * lse);
        }
        __syncthreads();
        if (tid < NE) atomicAdd(&g_probsum[tid], sp[tid]);
        if (tid == NE) atomicAdd(&g_zsum, *szp);
    } else {
        // ---------------- convw role ----------------
        int b2 = blockIdx.x - ROUTER_BLOCKS;
        int z = b2 >> 11;                    // /2048
        int rem = b2 & 2047;
        int bx = rem & 63;
        int by = rem >> 6;
        int mat = z / 9;
        int e = z % 9;
        __half* dst;
        const float* src;
        int K, N, n0, k0;
        if (mat == 0) {
            dst = g_wg; src = (e < NE) ? gw + (size_t)e * HD * ID : sgw;
            K = HD; N = ID; n0 = bx * 32; k0 = by * 32;
        } else if (mat == 1) {
            dst = g_wu; src = (e < NE) ? uw + (size_t)e * HD * ID : suw;
            K = HD; N = ID; n0 = bx * 32; k0 = by * 32;
        } else {
            dst = g_wd; src = (e < NE) ? dw + (size_t)e * ID * HD : sdw;
            K = ID; N = HD; n0 = by * 32; k0 = bx * 32;
        }
        float (*tile)[33] = (float (*)[33])sf;
        {
            int row = tid >> 3, f4 = tid & 7;
            float4 v = *(const float4*)(src + (size_t)(k0 + row) * N + n0 + f4 * 4);
            tile[row][f4 * 4 + 0] = v.x;
            tile[row][f4 * 4 + 1] = v.y;
            tile[row][f4 * 4 + 2] = v.z;
            tile[row][f4 * 4 + 3] = v.w;
        }
        __syncthreads();
        {
            int nr = tid >> 3, seg = tid & 7;
            int k = seg * 4;
            __half2 a, b;
            a.x = __float2half_rn(tile[k + 0][nr]);
            a.y = __float2half_rn(tile[k + 1][nr]);
            b.x = __float2half_rn(tile[k + 2][nr]);
            b.y = __float2half_rn(tile[k + 3][nr]);
            uint2 pk;
            pk.x = *(uint32_t*)&a;
            pk.y = *(uint32_t*)&b;
            *(uint2*)(dst + (size_t)e * K * N + (size_t)(n0 + nr) * K + k0 + k) = pk;
        }
    }
}

// ============================================================
// GEMM1 (mma.sync fp16, 4-stage cp.async pipeline): per CTA 128 rows x
// 64 cols of BOTH gate and up; fused SiLU epilogue -> g_act fp16.
// smem buffer: A | B(gate rows 0-63, up rows 64-127)
// ============================================================
__global__ __launch_bounds__(256) void gemm1_tc() {
    int e = blockIdx.z;
    int n = (e < NE) ? g_count[e] : T;
    int row0 = blockIdx.x * BM;
    if (row0 >= n) return;
    int j0 = blockIdx.y * 64;
    int tid = threadIdx.x;
    int lane = tid & 31;
    int wid = tid >> 5;
    int wm = wid & 3;            // M: 4 warps
    int wn = wid >> 2;           // N: 2 warps (32 cols each)

    extern __shared__ char smem[];
    uint32_t sb = s2u(smem);
    int* s_tok = (int*)(smem + SM_TOK);
    int* s_slot = (int*)(smem + SM_SLOT);

    if (tid < BM) {
        int pos = row0 + tid;
        int slot, tok;
        if (pos < n) {
            if (e < NE) { slot = g_elist[e * T + pos]; tok = slot >> 1; }
            else        { slot = ROWS_R + pos;         tok = pos; }
        } else {
            slot = -1;
            tok = (e < NE) ? (g_elist[e * T + row0] >> 1) : row0;
        }
        s_slot[tid] = slot;
        s_tok[tid] = tok;
    }
    __syncthreads();

    // loaders: 4 x 16B per thread per chunk (A: 2, B: 2)
    int r0 = tid >> 2, f0 = tid & 3;
    int r1 = r0 + 64;
    uint32_t off0 = (uint32_t)(r0 * RSB + f0 * 16);
    uint32_t off1 = (uint32_t)(r1 * RSB + f0 * 16);
    const char* pA0 = (const char*)(g_x + (size_t)s_tok[r0] * HD) + f0 * 16;
    const char* pA1 = (const char*)(g_x + (size_t)s_tok[r1] * HD) + f0 * 16;
    const char* pB0 = (const char*)(g_wg + ((size_t)e * ID + j0 + r0) * HD) + f0 * 16;
    const char* pB1 = (const char*)(g_wu + ((size_t)e * ID + j0 + r1 - 64) * HD) + f0 * 16;

#define G1_LOAD(bb) do { \
    CPA16((bb) + off0, pA0); CPA16((bb) + off1, pA1); \
    CPA16((bb) + PL + off0, pB0); CPA16((bb) + PL + off1, pB1); \
    pA0 += 64; pA1 += 64; pB0 += 64; pB1 += 64; \
    CP_COMMIT(); } while (0)

    float accg[2][4][4], accu[2][4][4];
#pragma unroll
    for (int mt = 0; mt < 2; mt++)
#pragma unroll
        for (int nt = 0; nt < 4; nt++)
#pragma unroll
            for (int c = 0; c < 4; c++) { accg[mt][nt][c] = 0.f; accu[mt][nt][c] = 0.f; }

    int lr = lane & 7;
    int aro = ((lane >> 3) & 1) * 8 + lr;     // A row-in-16
    int akb = (lane >> 4) * 16;               // A k-byte half
    int bro = ((lane >> 4) & 1) * 8 + lr;     // B row-in-16
    int bkb = ((lane >> 3) & 1) * 16;         // B k-byte half

    G1_LOAD(sb + SM_BUF0 + 0 * BUFB);
    G1_LOAD(sb + SM_BUF0 + 1 * BUFB);
    G1_LOAD(sb + SM_BUF0 + 2 * BUFB);

    for (int c = 0; c < NC1; c++) {
        if (c + 3 < NC1) G1_LOAD(sb + SM_BUF0 + ((c + 3) & 3) * BUFB);
        else CP_COMMIT();
        CP_WAIT3();
        __syncthreads();
        uint32_t bb = sb + SM_BUF0 + (c & 3) * BUFB;

#pragma unroll
        for (int ks = 0; ks < 2; ks++) {
            int kb = ks * 32;
            uint32_t ah[2][4];
#pragma unroll
            for (int mt = 0; mt < 2; mt++) {
                uint32_t ra = bb + (uint32_t)((wm * 32 + mt * 16 + aro) * RSB) + kb + akb;
                ldsm4(ah[mt], ra);
            }
            uint32_t bg[4][2], bu[4][2];
#pragma unroll
            for (int p = 0; p < 2; p++) {
                uint32_t rb = bb + PL + (uint32_t)((wn * 32 + p * 16 + bro) * RSB) + kb + bkb;
                uint32_t rg[4];
                ldsm4(rg, rb);
                bg[2 * p][0] = rg[0]; bg[2 * p][1] = rg[1];
                bg[2 * p + 1][0] = rg[2]; bg[2 * p + 1][1] = rg[3];
                ldsm4(rg, rb + 64 * RSB);
                bu[2 * p][0] = rg[0]; bu[2 * p][1] = rg[1];
                bu[2 * p + 1][0] = rg[2]; bu[2 * p + 1][1] = rg[3];
            }
#pragma unroll
            for (int mt = 0; mt < 2; mt++)
#pragma unroll
                for (int nt = 0; nt < 4; nt++) {
                    mma16816(accg[mt][nt], ah[mt], bg[nt]);
                    mma16816(accu[mt][nt], ah[mt], bu[nt]);
                }
        }
        __syncthreads();
    }
#undef G1_LOAD

    // ---- epilogue: silu(gate)*up -> fp16 ----
#pragma unroll
    for (int mt = 0; mt < 2; mt++) {
        int rA = wm * 32 + mt * 16 + (lane >> 2);
        int sl0 = s_slot[rA], sl1 = s_slot[rA + 8];
#pragma unroll
        for (int nt = 0; nt < 4; nt++) {
            int col = j0 + wn * 32 + nt * 8 + (lane & 3) * 2;
#pragma unroll
            for (int hhalf = 0; hhalf < 2; hhalf++) {
                int sl = hhalf ? sl1 : sl0;
                if (sl < 0) continue;
                float g0 = accg[mt][nt][hhalf * 2], g1 = accg[mt][nt][hhalf * 2 + 1];
                float u0 = accu[mt][nt][hhalf * 2], u1 = accu[mt][nt][hhalf * 2 + 1];
                float a0 = (g0 * u0) / (1.0f + __expf(-g0));
                float a1 = (g1 * u1) / (1.0f + __expf(-g1));
                __half2 hh;
                hh.x = __float2half_rn(a0); hh.y = __float2half_rn(a1);
                *(__half2*)(g_act + (size_t)sl * ID + col) = hh;
            }
        }
    }
}

// ============================================================
// GEMM2 (mma.sync fp16, 4-stage pipeline): per CTA 128 rows x 128 cols
// -> g_y fp32.
// ============================================================
__global__ __launch_bounds__(256) void gemm2_tc() {
    int e = blockIdx.z;
    int n = (e < NE) ? g_count[e] : T;
    int row0 = blockIdx.x * BM;
    if (row0 >= n) return;
    int j0 = blockIdx.y * 128;
    int tid = threadIdx.x;
    int lane = tid & 31;
    int wid = tid >> 5;
    int wm = wid & 3;
    int wn = wid >> 2;           // 2 warps x 64 cols

    extern __shared__ char smem[];
    uint32_t sb = s2u(smem);
    int* s_arow = (int*)(smem + SM_TOK);
    int* s_slot = (int*)(smem + SM_SLOT);

    if (tid < BM) {
        int pos = row0 + tid;
        int slot;
        if (pos < n) slot = (e < NE) ? g_elist[e * T + pos] : (ROWS_R + pos);
        else         slot = -1;
        s_slot[tid] = slot;
        s_arow[tid] = (slot >= 0) ? slot
                                  : ((e < NE) ? g_elist[e * T + row0] : (ROWS_R + row0));
    }
    __syncthreads();

    int r0 = tid >> 2, f0 = tid & 3;
    int r1 = r0 + 64;
    uint32_t off0 = (uint32_t)(r0 * RSB + f0 * 16);
    uint32_t off1 = (uint32_t)(r1 * RSB + f0 * 16);
    const char* pA0 = (const char*)(g_act + (size_t)s_arow[r0] * ID) + f0 * 16;
    const char* pA1 = (const char*)(g_act + (size_t)s_arow[r1] * ID) + f0 * 16;
    const char* pB0 = (const char*)(g_wd + ((size_t)e * HD + j0 + r0) * ID) + f0 * 16;
    const char* pB1 = (const char*)(g_wd + ((size_t)e * HD + j0 + r1) * ID) + f0 * 16;

#define G2_LOAD(bb) do { \
    CPA16((bb) + off0, pA0); CPA16((bb) + off1, pA1); \
    CPA16((bb) + PL + off0, pB0); CPA16((bb) + PL + off1, pB1); \
    pA0 += 64; pA1 += 64; pB0 += 64; pB1 += 64; \
    CP_COMMIT(); } while (0)

    float acc[2][8][4];
#pragma unroll
    for (int mt = 0; mt < 2; mt++)
#pragma unroll
        for (int nt = 0; nt < 8; nt++)
#pragma unroll
            for (int c = 0; c < 4; c++) acc[mt][nt][c] = 0.f;

    int lr = lane & 7;
    int aro = ((lane >> 3) & 1) * 8 + lr;
    int akb = (lane >> 4) * 16;
    int bro = ((lane >> 4) & 1) * 8 + lr;
    int bkb = ((lane >> 3) & 1) * 16;

    G2_LOAD(sb + SM_BUF0 + 0 * BUFB);
    G2_LOAD(sb + SM_BUF0 + 1 * BUFB);
    G2_LOAD(sb + SM_BUF0 + 2 * BUFB);

    for (int c = 0; c < NC2; c++) {
        if (c + 3 < NC2) G2_LOAD(sb + SM_BUF0 + ((c + 3) & 3) * BUFB);
        else CP_COMMIT();
        CP_WAIT3();
        __syncthreads();
        uint32_t bb = sb + SM_BUF0 + (c & 3) * BUFB;

#pragma unroll
        for (int ks = 0; ks < 2; ks++) {
            int kb = ks * 32;
            uint32_t ah[2][4];
#pragma unroll
            for (int mt = 0; mt < 2; mt++) {
                uint32_t ra = bb + (uint32_t)((wm * 32 + mt * 16 + aro) * RSB) + kb + akb;
                ldsm4(ah[mt], ra);
            }
            uint32_t bh[8][2];
#pragma unroll
            for (int p = 0; p < 4; p++) {
                uint32_t rb = bb + PL + (uint32_t)((wn * 64 + p * 16 + bro) * RSB) + kb + bkb;
                uint32_t rg[4];
                ldsm4(rg, rb);
                bh[2 * p][0] = rg[0]; bh[2 * p][1] = rg[1];
                bh[2 * p + 1][0] = rg[2]; bh[2 * p + 1][1] = rg[3];
            }
#pragma unroll
            for (int mt = 0; mt < 2; mt++)
#pragma unroll
                for (int nt = 0; nt < 8; nt++)
                    mma16816(acc[mt][nt], ah[mt], bh[nt]);
        }
        __syncthreads();
    }
#undef G2_LOAD

    // ---- epilogue: fp32 stores to g_y ----
#pragma unroll
    for (int mt = 0; mt < 2; mt++) {
        int rA = wm * 32 + mt * 16 + (lane >> 2);
        int sl0 = s_slot[rA], sl1 = s_slot[rA + 8];
#pragma unroll
        for (int nt = 0; nt < 8; nt++) {
            int col = j0 + wn * 64 + nt * 8 + (lane & 3) * 2;
            if (sl0 >= 0) {
                float2 v; v.x = acc[mt][nt][0]; v.y = acc[mt][nt][1];
                *(float2*)(g_y + (size_t)sl0 * HD + col) = v;
            }
            if (sl1 >= 0) {
                float2 v; v.x = acc[mt][nt][2]; v.y = acc[mt][nt][3];
                *(float2*)(g_y + (size_t)sl1 * HD + col) = v;
            }
        }
    }
}

// ============================================================
// combine: out[t] = w0*y[2t] + w1*y[2t+1] + y_shared[t]  (+ finalize in blk 0)
// ============================================================
__global__ void combine_kernel(float* __restrict__ out) {
    if (blockIdx.x == 0 && threadIdx.x == 0) {
        float aux = 0.f;
#pragma unroll
        for (int e = 0; e < NE; e++)
            aux += ((float)g_count[e] / (2.0f * (float)T)) * (g_probsum[e] / (float)T);
        out[OUT_AUX] = (float)NE * aux;
        out[OUT_Z] = g_zsum / (float)T;
    }
    int idx = blockIdx.x * blockDim.x + threadIdx.x;
    int t = idx / (HD / 4);
    int c = (idx % (HD / 4)) * 4;
    float w0 = g_wslot[2 * t];
    float w1 = g_wslot[2 * t + 1];
    float4 y0 = *(const float4*)(g_y + (size_t)(2 * t) * HD + c);
    float4 y1 = *(const float4*)(g_y + (size_t)(2 * t + 1) * HD + c);
    float4 ys = *(const float4*)(g_y + (size_t)(ROWS_R + t) * HD + c);
    float4 r;
    r.x = fmaf(w0, y0.x, fmaf(w1, y1.x, ys.x));
    r.y = fmaf(w0, y0.y, fmaf(w1, y1.y, ys.y));
    r.z = fmaf(w0, y0.z, fmaf(w1, y1.z, ys.z));
    r.w = fmaf(w0, y0.w, fmaf(w1, y1.w, ys.w));
    *(float4*)(out + (size_t)t * HD + c) = r;
}

// ============================================================
extern "C" void kernel_launch(void* const* d_in, const int* in_sizes, int n_in,
                              void* d_out, int out_size) {
    const float* x   = (const float*)d_in[0];
    const float* rw  = (const float*)d_in[1];
    const float* gw  = (const float*)d_in[2];
    const float* uw  = (const float*)d_in[3];
    const float* dw  = (const float*)d_in[4];
    const float* sgw = (const float*)d_in[5];
    const float* suw = (const float*)d_in[6];
    const float* sdw = (const float*)d_in[7];
    float* out = (float*)d_out;

    cudaFuncSetAttribute(gemm1_tc, cudaFuncAttributeMaxDynamicSharedMemorySize, SMEM_BYTES);
    cudaFuncSetAttribute(gemm2_tc, cudaFuncAttributeMaxDynamicSharedMemorySize, SMEM_BYTES);

    reset_kernel<<<1, 32>>>();
    fused_pre_kernel<<<ROUTER_BLOCKS + CONVW_BLOCKS, 256>>>(
        x, rw, out, gw, uw, dw, sgw, suw, sdw);
    gemm1_tc<<<dim3(T / BM, ID / 64, NE + 1), 256, SMEM_BYTES>>>();
    gemm2_tc<<<dim3(T / BM, HD / 128, NE + 1), 256, SMEM_BYTES>>>();
    combine_kernel<<<(T * HD / 4) / 256, 256>>>(out);
}